// round 1
// baseline (speedup 1.0000x reference)
#include <cuda_runtime.h>
#include <math.h>

#define W 512
#define F 257
#define HOP 128
#define FT 4
#define MAXT 1300

// ---- static device scratch (no allocations allowed) ----
__device__ float2 g_tw[W * F];          // (cos, sin) twiddles, layout [n][f]
__device__ float  g_hann[W];
__device__ float  g_bark[F], g_dshift[F], g_athdb[F], g_athpow[F];
__device__ float  g_psd [MAXT * F];     // ref psd in dB (clamped at -200)
__device__ float  g_pdel[MAXT * F];     // delta linear power (unscaled)
__device__ float  g_thr [MAXT * F];     // threshold POWER (10^(thr/10))
__device__ float  g_pmax_part[512];
__device__ float  g_psd_max;
__device__ double g_acc;

// ---------------------------------------------------------------------------
// Kernel 1: build constant tables (double precision, cast to fp32 like ref)
// ---------------------------------------------------------------------------
__global__ void init_tables() {
    int idx = blockIdx.x * blockDim.x + threadIdx.x;
    if (idx < W * F) {
        int n = idx / F, f = idx % F;
        double s, c;
        sincospi(-2.0 * (double)(n * f) / (double)W, &s, &c);
        g_tw[idx] = make_float2((float)c, (float)s);
    }
    if (idx < W) {
        g_hann[idx] = (float)(0.5 * (1.0 - cospi(2.0 * (double)idx / (double)W)));
    }
    if (idx < F) {
        double freq = (double)idx * (8000.0 / 256.0);
        double bark = 13.0 * atan(0.00076 * freq)
                    + 3.5  * atan((freq / 7500.0) * (freq / 7500.0));
        float bf = (float)bark;
        g_bark[idx]   = bf;
        g_dshift[idx] = -6.025f - 0.275f * bf;
        if (freq >= 20.0 && freq <= 20000.0) {
            double fk = freq * 0.001;
            double ath = 3.64 * pow(fk, -0.8)
                       - 6.5  * exp(-0.6 * (fk - 3.3) * (fk - 3.3))
                       + 0.001 * fk * fk * fk * fk
                       - 12.0;
            float athf = (float)ath;
            g_athdb[idx]  = athf;
            g_athpow[idx] = exp10f(athf * 0.1f);
        } else {
            g_athdb[idx]  = -INFINITY;
            g_athpow[idx] = 0.0f;
        }
    }
}

// ---------------------------------------------------------------------------
// Kernel 2: STFT power for ref and delta, FT frames per CTA.
//   psd_ref (dB, clamped) -> g_psd ;  |S_delta|^2 * (GAIN/W)^2 -> g_pdel
//   per-CTA psd max -> g_pmax_part
// ---------------------------------------------------------------------------
__global__ void __launch_bounds__(288) stft_kernel(
    const float* __restrict__ xadv, const float* __restrict__ xref, int T)
{
    __shared__ float2 xw[FT][W];     // .x = ref*hann, .y = (adv-ref)*hann
    __shared__ float  wmax[16];

    int tid = threadIdx.x;
    int t0  = blockIdx.x * FT;

    for (int idx = tid; idx < FT * W; idx += 288) {
        int j = idx >> 9, n = idx & (W - 1);
        float2 v = make_float2(0.f, 0.f);
        int t = t0 + j;
        if (t < T) {
            int g = t * HOP + n;
            float r = xref[g], a = xadv[g], h = g_hann[n];
            v.x = r * h;
            v.y = (a - r) * h;
        }
        xw[j][n] = v;
    }
    __syncthreads();

    float lmax = -1e30f;
    if (tid < F) {
        int f = tid;
        float rr[FT], ir[FT], rd[FT], id_[FT];
#pragma unroll
        for (int j = 0; j < FT; j++) { rr[j] = ir[j] = rd[j] = id_[j] = 0.f; }

        const float2* tw = g_tw + f;
#pragma unroll 4
        for (int n = 0; n < W; n++) {
            float2 cs = tw[n * F];
#pragma unroll
            for (int j = 0; j < FT; j++) {
                float2 x = xw[j][n];
                rr[j]  = fmaf(x.x, cs.x, rr[j]);
                ir[j]  = fmaf(x.x, cs.y, ir[j]);
                rd[j]  = fmaf(x.y, cs.x, rd[j]);
                id_[j] = fmaf(x.y, cs.y, id_[j]);
            }
        }
        const float gw2 = 1.0172526041666667e-5f;   // (8/3) / 512^2
#pragma unroll
        for (int j = 0; j < FT; j++) {
            int t = t0 + j;
            if (t < T) {
                float Pr  = gw2 * (rr[j] * rr[j] + ir[j] * ir[j]);
                float psd = fmaxf(10.f * log10f(Pr), -200.f);
                g_psd[t * F + f]  = psd;
                lmax = fmaxf(lmax, psd);
                g_pdel[t * F + f] = gw2 * (rd[j] * rd[j] + id_[j] * id_[j]);
            }
        }
    }
    // block max reduce (9 warps)
#pragma unroll
    for (int o = 16; o > 0; o >>= 1)
        lmax = fmaxf(lmax, __shfl_xor_sync(0xFFFFFFFFu, lmax, o));
    if ((tid & 31) == 0) wmax[tid >> 5] = lmax;
    __syncthreads();
    if (tid == 0) {
        float m = wmax[0];
        for (int w = 1; w < 9; w++) m = fmaxf(m, wmax[w]);
        g_pmax_part[blockIdx.x] = m;
    }
}

// ---------------------------------------------------------------------------
// Kernel 3: finish psd_max reduction, zero loss accumulator
// ---------------------------------------------------------------------------
__global__ void reduce_finish(int nb) {
    __shared__ float sm[512];
    int tid = threadIdx.x;
    float v = -1e30f;
    for (int i = tid; i < nb; i += 512) v = fmaxf(v, g_pmax_part[i]);
    sm[tid] = v;
    __syncthreads();
    for (int s = 256; s > 0; s >>= 1) {
        if (tid < s) sm[tid] = fmaxf(sm[tid], sm[tid + s]);
        __syncthreads();
    }
    if (tid == 0) { g_psd_max = sm[0]; g_acc = 0.0; }
}

// ---------------------------------------------------------------------------
// Kernel 4: per-frame masking threshold (power domain). One CTA per frame.
// ---------------------------------------------------------------------------
__global__ void __launch_bounds__(256) thresh_kernel(int T) {
    __shared__ float p[F], pw[F], mall[F], mc[F];
    __shared__ float mz[F], mbase[F], msp[F];
    __shared__ short order[F];
    __shared__ unsigned char validf[F], keepf[F];
    __shared__ int kcnt;

    int t   = blockIdx.x;
    int tid = threadIdx.x;
    float pm = g_psd_max;

    for (int f = tid; f < F; f += 256) {
        float pv = 96.f - pm + g_psd[t * F + f];
        p[f]  = pv;
        pw[f] = exp10f(pv * 0.1f);
    }
    __syncthreads();

    for (int f = tid; f < F; f += 256) {
        int fm = (f == 0)     ? F - 1 : f - 1;
        int fp = (f == F - 1) ? 0     : f + 1;
        float m = 10.f * log10f(pw[fm] + pw[f] + pw[fp]);
        mall[f] = m;
        bool ismax = (f > 0) && (f < F - 1) && (p[f] > p[f - 1]) && (p[f] > p[f + 1]);
        validf[f] = (unsigned char)(ismax && (m > g_athdb[f]));
    }
    __syncthreads();

    if (tid == 0) {
        // stable compaction: valid bins first, in frequency order
        int n = 0;
        for (int f = 0; f < F; f++) {
            if (validf[f]) { order[n] = (short)f; mc[n] = mall[f]; n++; }
        }
        for (int i = 0; i < F; i++) keepf[i] = 1;
        // faithful replication of the reference's sequential dedup scan
        // (bark indexed by LIST POSITION, as in the source)
        int ip = 0;
        for (int i = 1; i < F; i++) {
            if (i < n) {
                bool close = (g_bark[i] - g_bark[ip]) < 0.5f;
                bool psm   = mc[ip] < mc[i];
                if (close) {
                    keepf[psm ? ip : i] = 0;
                    ip = psm ? ip + 1 : ip;
                } else {
                    ip = i;
                }
            }
        }
        // compact kept maskers with precomputed spreading constants
        int K = 0;
        for (int k = 0; k < n; k++) {
            if (keepf[k]) {
                int o = order[k];
                mz[K]    = g_bark[o];
                mbase[K] = mc[k] + g_dshift[o];
                msp[K]   = -27.f + 0.37f * fmaxf(mc[k] - 40.f, 0.f);
                K++;
            }
        }
        kcnt = K;
    }
    __syncthreads();

    int K = kcnt;
    for (int f = tid; f < F; f += 256) {
        float sum = g_athpow[f];
        float bf  = g_bark[f];
        for (int k = 0; k < K; k++) {
            float dz = bf - mz[k];
            float sl = (dz > 0.f) ? msp[k] : 27.f;
            sum += exp10f((mbase[k] + sl * dz) * 0.1f);
        }
        g_thr[t * F + f] = sum;   // threshold power = 10^(thr_dB/10)
    }
}

// ---------------------------------------------------------------------------
// Kernel 5: loss = sum relu(scale * pdel - thr_pow), double accumulation
// ---------------------------------------------------------------------------
__global__ void __launch_bounds__(256) loss_kernel(int N) {
    float sc = exp10f(9.6f - 0.1f * g_psd_max);
    double local = 0.0;
    for (int i = blockIdx.x * blockDim.x + threadIdx.x; i < N;
         i += gridDim.x * blockDim.x) {
        float v = fmaf(sc, g_pdel[i], -g_thr[i]);
        if (v > 0.f) local += (double)v;
    }
    __shared__ double sd[256];
    int tid = threadIdx.x;
    sd[tid] = local;
    __syncthreads();
    for (int s = 128; s > 0; s >>= 1) {
        if (tid < s) sd[tid] += sd[tid + s];
        __syncthreads();
    }
    if (tid == 0) atomicAdd(&g_acc, sd[0]);
}

__global__ void finalize_kernel(float* out, int N) {
    out[0] = (float)(1e-6 * g_acc / (double)N);
}

// ---------------------------------------------------------------------------
extern "C" void kernel_launch(void* const* d_in, const int* in_sizes, int n_in,
                              void* d_out, int out_size)
{
    const float* xadv = (const float*)d_in[0];
    const float* xref = (const float*)d_in[1];
    float* out = (float*)d_out;

    int L = in_sizes[0];
    int T = (L - W) / HOP + 1;          // 1247 for L=160000
    if (T > MAXT) T = MAXT;
    int N  = T * F;
    int nb = (T + FT - 1) / FT;

    init_tables<<<(W * F + 255) / 256, 256>>>();
    stft_kernel<<<nb, 288>>>(xadv, xref, T);
    reduce_finish<<<1, 512>>>(nb);
    thresh_kernel<<<T, 256>>>(T);
    loss_kernel<<<256, 256>>>(N);
    finalize_kernel<<<1, 1>>>(out, N);
}

// round 2
// speedup vs baseline: 1.4890x; 1.4890x over previous
#include <cuda_runtime.h>
#include <math.h>

#define W 512
#define F 257
#define HOP 128
#define FT 4
#define MAXT 1300
#define STFT_THREADS 288

// ---- static device scratch ----
__device__ float  g_cos[512], g_sin[512], g_hann[512];
__device__ float  g_bark[F], g_dshift[F], g_athdb[F], g_athpow[F];
__device__ float  g_psd [MAXT * F];     // ref psd dB (clamped -200)
__device__ float  g_pdel[MAXT * F];     // delta linear power (unscaled)
__device__ float  g_pmax_part[512];
__device__ float  g_psd_max;
__device__ double g_acc;

// ---------------------------------------------------------------------------
// Kernel 1: tiny constant tables (512 twiddles via mod-512 structure)
// ---------------------------------------------------------------------------
__global__ void init_tables() {
    int i = threadIdx.x;
    if (i < 512) {
        double s, c;
        sincospi(2.0 * (double)i / 512.0, &s, &c);
        g_cos[i] = (float)c;
        g_sin[i] = (float)s;
        g_hann[i] = (float)(0.5 * (1.0 - cospi(2.0 * (double)i / 512.0)));
    }
    if (i < F) {
        double freq = (double)i * (8000.0 / 256.0);
        double bark = 13.0 * atan(0.00076 * freq)
                    + 3.5  * atan((freq / 7500.0) * (freq / 7500.0));
        float bf = (float)bark;
        g_bark[i]   = bf;
        g_dshift[i] = -6.025f - 0.275f * bf;
        if (freq >= 20.0 && freq <= 20000.0) {
            double fk = freq * 0.001;
            double ath = 3.64 * pow(fk, -0.8)
                       - 6.5  * exp(-0.6 * (fk - 3.3) * (fk - 3.3))
                       + 0.001 * fk * fk * fk * fk
                       - 12.0;
            float athf = (float)ath;
            g_athdb[i]  = athf;
            g_athpow[i] = exp10f(athf * 0.1f);
        } else {
            g_athdb[i]  = -INFINITY;
            g_athpow[i] = 0.0f;
        }
    }
}

// ---------------------------------------------------------------------------
// Kernel 2: STFT via even/odd symmetry + 512-entry smem twiddle table.
// ---------------------------------------------------------------------------
__global__ void __launch_bounds__(STFT_THREADS) stft_kernel(
    const float* __restrict__ xadv, const float* __restrict__ xref, int T)
{
    __shared__ float4 eo[FT][256];      // [j][n]: e_ref, o_ref, e_del, o_del
    __shared__ float  tc[528], ts[528]; // padded twiddles: idx = k + (k>>5)
    __shared__ float  wmax[10];

    int tid = threadIdx.x;
    int t0  = blockIdx.x * FT;

    for (int k = tid; k < 512; k += STFT_THREADS) {
        int pk = k + (k >> 5);
        tc[pk] = g_cos[k];
        ts[pk] = g_sin[k];
    }
    for (int idx = tid; idx < FT * 256; idx += STFT_THREADS) {
        int j = idx >> 8, n = idx & 255;
        float4 v = make_float4(0.f, 0.f, 0.f, 0.f);
        int t = t0 + j;
        if (t < T) {
            int g = t * HOP;
            if (n == 0) {
                // slot 0 carries the hann-weighted edge sample x[256] (h[256]=1, h[0]=0)
                float r = xref[g + 256], a = xadv[g + 256];
                v.x = r;            // ref edge
                v.z = a - r;        // delta edge
            } else {
                float h  = g_hann[n];
                float r1 = xref[g + n], r2 = xref[g + 512 - n];
                float a1 = xadv[g + n], a2 = xadv[g + 512 - n];
                float d1 = a1 - r1,     d2 = a2 - r2;
                v.x = h * (r1 + r2);
                v.y = h * (r1 - r2);
                v.z = h * (d1 + d2);
                v.w = h * (d1 - d2);
            }
        }
        eo[j][n] = v;
    }
    __syncthreads();

    float lmax = -1e30f;
    if (tid < F) {
        int f = tid;
        float sgn = (f & 1) ? -1.f : 1.f;
        float rr[FT], ir[FT], rd[FT], idl[FT];
#pragma unroll
        for (int j = 0; j < FT; j++) {
            float4 v0 = eo[j][0];
            rr[j] = sgn * v0.x;  rd[j] = sgn * v0.z;
            ir[j] = 0.f;         idl[j] = 0.f;
        }
        int k = f;   // k = (n*f) mod 512, starting at n=1
#pragma unroll 4
        for (int n = 1; n < 256; n++) {
            int pk = k + (k >> 5);
            float c = tc[pk], s = ts[pk];
#pragma unroll
            for (int j = 0; j < FT; j++) {
                float4 v = eo[j][n];
                rr[j]  = fmaf(v.x, c, rr[j]);
                ir[j]  = fmaf(v.y, s, ir[j]);
                rd[j]  = fmaf(v.z, c, rd[j]);
                idl[j] = fmaf(v.w, s, idl[j]);
            }
            k = (k + f) & 511;
        }
        const float gw2 = 1.0172526041666667e-5f;   // (8/3)/512^2
#pragma unroll
        for (int j = 0; j < FT; j++) {
            int t = t0 + j;
            if (t < T) {
                float Pr  = gw2 * (rr[j] * rr[j] + ir[j] * ir[j]);
                float psd = fmaxf(10.f * log10f(Pr), -200.f);
                g_psd[t * F + f]  = psd;
                lmax = fmaxf(lmax, psd);
                g_pdel[t * F + f] = gw2 * (rd[j] * rd[j] + idl[j] * idl[j]);
            }
        }
    }
#pragma unroll
    for (int o = 16; o > 0; o >>= 1)
        lmax = fmaxf(lmax, __shfl_xor_sync(0xFFFFFFFFu, lmax, o));
    if ((tid & 31) == 0) wmax[tid >> 5] = lmax;
    __syncthreads();
    if (tid == 0) {
        float m = wmax[0];
        for (int w = 1; w < 9; w++) m = fmaxf(m, wmax[w]);
        g_pmax_part[blockIdx.x] = m;
    }
}

// ---------------------------------------------------------------------------
// Kernel 3: finish psd_max reduction, zero loss accumulator
// ---------------------------------------------------------------------------
__global__ void reduce_finish(int nb) {
    __shared__ float sm[512];
    int tid = threadIdx.x;
    float v = -1e30f;
    for (int i = tid; i < nb; i += 512) v = fmaxf(v, g_pmax_part[i]);
    sm[tid] = v;
    __syncthreads();
    for (int s = 256; s > 0; s >>= 1) {
        if (tid < s) sm[tid] = fmaxf(sm[tid], sm[tid + s]);
        __syncthreads();
    }
    if (tid == 0) { g_psd_max = sm[0]; g_acc = 0.0; }
}

// ---------------------------------------------------------------------------
// Kernel 4: per-frame masking threshold + FUSED loss. One CTA per frame.
// ---------------------------------------------------------------------------
__global__ void __launch_bounds__(256) thresh_kernel(int T) {
    __shared__ float pp[F], pw[F], mall[F], sb[F];
    __shared__ float mc[F];
    __shared__ short order[F];
    __shared__ unsigned char validf[F], keepf[F];
    __shared__ int   warpcnt[8], warpbase[8];
    __shared__ int   nsh, Ksh;
    __shared__ float mz[F], mbase[F], msp[F];
    __shared__ float red[8];

    int t   = blockIdx.x;
    int tid = threadIdx.x;
    float pm = g_psd_max;

    for (int f = tid; f < F; f += 256) {
        float pv = 96.f - pm + g_psd[t * F + f];
        pp[f] = pv;
        pw[f] = exp10f(pv * 0.1f);
        sb[f] = g_bark[f];
    }
    __syncthreads();

    for (int f = tid; f < F; f += 256) {
        int fm = (f == 0)     ? F - 1 : f - 1;
        int fp = (f == F - 1) ? 0     : f + 1;
        float m = 10.f * log10f(pw[fm] + pw[f] + pw[fp]);
        mall[f] = m;
        bool ismax = (f > 0) && (f < F - 1) && (pp[f] > pp[f - 1]) && (pp[f] > pp[f + 1]);
        validf[f] = (unsigned char)(ismax && (m > g_athdb[f]));
        keepf[f]  = 1;
    }
    __syncthreads();

    // parallel stable compaction over f in [0,256) (validf[0]=validf[256]=0 always)
    {
        int w = tid >> 5, l = tid & 31;
        bool v = validf[tid];
        unsigned m = __ballot_sync(0xFFFFFFFFu, v);
        if (l == 0) warpcnt[w] = __popc(m);
        __syncthreads();
        if (tid == 0) {
            int s = 0;
            for (int i = 0; i < 8; i++) { warpbase[i] = s; s += warpcnt[i]; }
            nsh = s;
        }
        __syncthreads();
        if (v) {
            int pos = warpbase[w] + __popc(m & ((1u << l) - 1u));
            order[pos] = (short)tid;
            mc[pos]    = mall[tid];
        }
    }
    __syncthreads();

    if (tid < 32) {
        int n = nsh;
        if (tid == 0) {
            // faithful sequential dedup (bark indexed by LIST POSITION, as in ref)
            int ip = 0;
            for (int i = 1; i < n; i++) {
                bool close = (sb[i] - sb[ip]) < 0.5f;
                if (close) {
                    bool psm = mc[ip] < mc[i];
                    keepf[psm ? ip : i] = 0;
                    if (psm) ip = ip + 1;
                } else {
                    ip = i;
                }
            }
        }
        __syncwarp();
        // warp-ballot compaction of kept maskers (frequency order preserved)
        int base = 0;
        for (int c0 = 0; c0 < n; c0 += 32) {
            int i = c0 + tid;
            bool ok = (i < n) && keepf[i];
            unsigned m = __ballot_sync(0xFFFFFFFFu, ok);
            if (ok) {
                int pos = base + __popc(m & ((1u << tid) - 1u));
                int o   = order[i];
                float mv = mc[i];
                mz[pos]    = sb[o];
                mbase[pos] = mv + g_dshift[o];
                msp[pos]   = fmaf(0.37f, fmaxf(mv - 40.f, 0.f), -27.f);
            }
            base += __popc(m);
        }
        if (tid == 0) Ksh = base;
    }
    __syncthreads();

    int K = Ksh;
    float sc = exp10f(fmaf(-0.1f, pm, 9.6f));
    float lsum = 0.f;
    for (int f = tid; f < F; f += 256) {
        float sum = g_athpow[f];
        float bf  = sb[f];
        for (int k = 0; k < K; k++) {
            float dz = bf - mz[k];
            float sl = (dz > 0.f) ? msp[k] : 27.f;
            sum += exp10f(0.1f * fmaf(sl, dz, mbase[k]));
        }
        float v = fmaf(sc, g_pdel[t * F + f], -sum);
        if (v > 0.f) lsum += v;
    }
#pragma unroll
    for (int o = 16; o > 0; o >>= 1)
        lsum += __shfl_xor_sync(0xFFFFFFFFu, lsum, o);
    if ((tid & 31) == 0) red[tid >> 5] = lsum;
    __syncthreads();
    if (tid == 0) {
        float s = 0.f;
        for (int w = 0; w < 8; w++) s += red[w];
        atomicAdd(&g_acc, (double)s);
    }
}

__global__ void finalize_kernel(float* out, int N) {
    out[0] = (float)(1e-6 * g_acc / (double)N);
}

// ---------------------------------------------------------------------------
extern "C" void kernel_launch(void* const* d_in, const int* in_sizes, int n_in,
                              void* d_out, int out_size)
{
    const float* xadv = (const float*)d_in[0];
    const float* xref = (const float*)d_in[1];
    float* out = (float*)d_out;

    int L = in_sizes[0];
    int T = (L - W) / HOP + 1;          // 1247 for L=160000
    if (T > MAXT) T = MAXT;
    int N  = T * F;
    int nb = (T + FT - 1) / FT;

    init_tables<<<1, 512>>>();
    stft_kernel<<<nb, STFT_THREADS>>>(xadv, xref, T);
    reduce_finish<<<1, 512>>>(nb);
    thresh_kernel<<<T, 256>>>(T);
    finalize_kernel<<<1, 1>>>(out, N);
}

// round 4
// speedup vs baseline: 1.9862x; 1.3339x over previous
#include <cuda_runtime.h>
#include <math.h>

#define W 512
#define F 257
#define HOP 128
#define FT 6
#define MAXT 1300
#define SPAN (W + (FT - 1) * HOP)   // 1152
#define STHREADS 160

// ---- static device scratch ----
__device__ float  g_cos[512], g_sin[512], g_hann[512];
__device__ float  g_bark[F], g_dshift[F], g_athpow[F];
__device__ float  g_pr  [MAXT * F];    // ref linear power
__device__ float  g_pdel[MAXT * F];    // delta linear power
__device__ float  g_pmax_part[512];
__device__ float  g_psd_max;
__device__ double g_acc;

// ---------------------------------------------------------------------------
// Kernel 1: constant tables
// ---------------------------------------------------------------------------
__global__ void init_tables() {
    int i = threadIdx.x;
    if (i < 512) {
        double s, c;
        sincospi(2.0 * (double)i / 512.0, &s, &c);
        g_cos[i]  = (float)c;
        g_sin[i]  = (float)s;
        g_hann[i] = (float)(0.5 * (1.0 - cospi(2.0 * (double)i / 512.0)));
    }
    if (i < F) {
        double freq = (double)i * (8000.0 / 256.0);
        double bark = 13.0 * atan(0.00076 * freq)
                    + 3.5  * atan((freq / 7500.0) * (freq / 7500.0));
        float bf = (float)bark;
        g_bark[i]   = bf;
        g_dshift[i] = -6.025f - 0.275f * bf;
        if (freq >= 20.0 && freq <= 20000.0) {
            double fk = freq * 0.001;
            double ath = 3.64 * pow(fk, -0.8)
                       - 6.5  * exp(-0.6 * (fk - 3.3) * (fk - 3.3))
                       + 0.001 * fk * fk * fk * fk
                       - 12.0;
            g_athpow[i] = exp10f((float)ath * 0.1f);
        } else {
            g_athpow[i] = 0.0f;   // ATH = -inf  ->  power 0 (compare always true)
        }
    }
}

// ---------------------------------------------------------------------------
// Kernel 2: STFT, doubly-folded real DFT. blockIdx.y = frequency parity.
//   rr = (-1)^f x[256] + e128*cos(pi f/2) + sum_{n=1..127} [e_n + (-1)^f e_{256-n}] cos
//   ii =               o128*sin(pi f/2) + sum_{n=1..127} [o_n - (-1)^f o_{256-n}] sin
// ---------------------------------------------------------------------------
__global__ void __launch_bounds__(STHREADS) stft_kernel(
    const float* __restrict__ xadv, const float* __restrict__ xref,
    int T, int Lv)
{
    __shared__ float  xr[SPAN], xd[SPAN];
    __shared__ float4 eo[FT][128];   // [j][n]: ce_ref, co_ref, ce_del, co_del
    __shared__ float  edge[FT][8];   // x256r,e128r,o128r,x256d,e128d,o128d
    __shared__ float  tc[528], ts[528];
    __shared__ float  wmax[5];

    int tid = threadIdx.x;
    int par = blockIdx.y;            // 0: even f, 1: odd f
    int t0  = blockIdx.x * FT;
    int base = t0 * HOP;

    for (int k = tid; k < 512; k += STHREADS) {
        int pk = k + (k >> 5);
        tc[pk] = g_cos[k];
        ts[pk] = g_sin[k];
    }
    for (int i = tid; i < SPAN; i += STHREADS) {
        int g = base + i;
        float r = 0.f, d = 0.f;
        if (g < Lv) { r = xref[g]; d = xadv[g] - r; }
        xr[i] = r; xd[i] = d;
    }
    __syncthreads();

    float s = par ? -1.f : 1.f;
    for (int idx = tid; idx < FT * 128; idx += STHREADS) {
        int j = idx >> 7, n = idx & 127;
        const float* fr = xr + j * HOP;
        const float* fd = xd + j * HOP;
        if (n == 0) {
            edge[j][0] = fr[256];
            edge[j][1] = (fr[128] + fr[384]) * 0.5f;
            edge[j][2] = (fr[128] - fr[384]) * 0.5f;
            edge[j][3] = fd[256];
            edge[j][4] = (fd[128] + fd[384]) * 0.5f;
            edge[j][5] = (fd[128] - fd[384]) * 0.5f;
        } else {
            float h1 = g_hann[n], h2 = g_hann[256 - n];
            float a1 = fr[n], a2 = fr[512 - n], a3 = fr[256 - n], a4 = fr[256 + n];
            float b1 = fd[n], b2 = fd[512 - n], b3 = fd[256 - n], b4 = fd[256 + n];
            float er1 = (a1 + a2) * h1, er2 = (a3 + a4) * h2;
            float or1 = (a1 - a2) * h1, or2 = (a3 - a4) * h2;
            float ed1 = (b1 + b2) * h1, ed2 = (b3 + b4) * h2;
            float od1 = (b1 - b2) * h1, od2 = (b3 - b4) * h2;
            eo[j][n] = make_float4(er1 + s * er2, or1 - s * or2,
                                   ed1 + s * ed2, od1 - s * od2);
        }
    }
    __syncthreads();

    float lmax = 0.f;
    int nf = 129 - par;              // even: f=0..256 (129), odd: f=1..255 (128)
    if (tid < nf) {
        int i = tid, f = 2 * i + par;
        float sgn = (i & 1) ? -1.f : 1.f;
        float rr[FT], ii[FT], rd[FT], id_[FT];
#pragma unroll
        for (int j = 0; j < FT; j++) {
            if (par == 0) {
                rr[j]  = fmaf(sgn, edge[j][1], edge[j][0]);
                ii[j]  = 0.f;
                rd[j]  = fmaf(sgn, edge[j][4], edge[j][3]);
                id_[j] = 0.f;
            } else {
                rr[j]  = -edge[j][0];
                ii[j]  = sgn * edge[j][2];
                rd[j]  = -edge[j][3];
                id_[j] = sgn * edge[j][5];
            }
        }
        int k = f;                   // k = (n*f) mod 512, n starting at 1
#pragma unroll 4
        for (int n = 1; n < 128; n++) {
            int pk = k + (k >> 5);
            float c = tc[pk], sn = ts[pk];
#pragma unroll
            for (int j = 0; j < FT; j++) {
                float4 v = eo[j][n];
                rr[j]  = fmaf(v.x, c,  rr[j]);
                ii[j]  = fmaf(v.y, sn, ii[j]);
                rd[j]  = fmaf(v.z, c,  rd[j]);
                id_[j] = fmaf(v.w, sn, id_[j]);
            }
            k = (k + f) & 511;
        }
        const float gw2 = 1.0172526041666667e-5f;   // (8/3)/512^2
#pragma unroll
        for (int j = 0; j < FT; j++) {
            int t = t0 + j;
            if (t < T) {
                float Pr = gw2 * (rr[j] * rr[j] + ii[j] * ii[j]);
                g_pr[t * F + f]   = Pr;
                lmax = fmaxf(lmax, Pr);
                g_pdel[t * F + f] = gw2 * (rd[j] * rd[j] + id_[j] * id_[j]);
            }
        }
    }
#pragma unroll
    for (int o = 16; o > 0; o >>= 1)
        lmax = fmaxf(lmax, __shfl_xor_sync(0xFFFFFFFFu, lmax, o));
    if ((tid & 31) == 0) wmax[tid >> 5] = lmax;
    __syncthreads();
    if (tid == 0) {
        float m = wmax[0];
        for (int wv = 1; wv < 5; wv++) m = fmaxf(m, wmax[wv]);
        g_pmax_part[blockIdx.y * gridDim.x + blockIdx.x] = m;
    }
}

// ---------------------------------------------------------------------------
// Kernel 3: finish psd_max (dB), zero accumulator
// ---------------------------------------------------------------------------
__global__ void reduce_finish(int nb) {
    __shared__ float sm[512];
    int tid = threadIdx.x;
    float v = 0.f;
    for (int i = tid; i < nb; i += 512) v = fmaxf(v, g_pmax_part[i]);
    sm[tid] = v;
    __syncthreads();
    for (int s = 256; s > 0; s >>= 1) {
        if (tid < s) sm[tid] = fmaxf(sm[tid], sm[tid + s]);
        __syncthreads();
    }
    if (tid == 0) {
        g_psd_max = 10.f * log10f(fmaxf(sm[0], 1e-20f));
        g_acc = 0.0;
    }
}

#define BART() asm volatile("bar.sync %0, 128;" :: "r"(team + 1) : "memory")

// ---------------------------------------------------------------------------
// Kernel 4: masking threshold + fused loss; TWO frames per CTA (128-thr teams)
// ---------------------------------------------------------------------------
__global__ void __launch_bounds__(256) thresh_kernel(int T) {
    __shared__ float sb[F];
    __shared__ float pw[2][F];
    __shared__ float mcv[2][128];
    __shared__ float mz[2][128], mb2[2][128], ms2[2][128];
    __shared__ short order[2][128];
    __shared__ unsigned char keepf[2][128];
    __shared__ int   cnt[2][8], cbase[2][8];
    __shared__ int   nsh[2], Ksh[2];
    __shared__ float red[2][4];

    int tid  = threadIdx.x;
    int team = tid >> 7;
    int lt   = tid & 127;
    int w    = lt >> 5, l = lt & 31;
    int t    = blockIdx.x * 2 + team;
    float pm = g_psd_max;

    for (int f = tid; f < F; f += 256) sb[f] = g_bark[f];
    __syncthreads();
    if (t >= T) return;

    const float LG = 0.33219280948873623f;   // 0.1*log2(10)
    float C = exp10f(0.1f * (96.f - pm));
    const float* prp = g_pr + t * F;
    for (int f = lt; f < F; f += 128)
        pw[team][f] = C * fmaxf(prp[f], 1e-20f);
    keepf[team][lt] = 1;
    BART();

    // local-max + ATH test for f=lt (chunk w) and f=lt+128 (chunk 4+w).
    float p3A = 0.f, p3B = 0.f;
    bool  vA = false, vB = false;
    {
        int f = lt;
        if (f >= 1) {
            float cm = pw[team][f - 1], c0 = pw[team][f], cp = pw[team][f + 1];
            p3A = cm + c0 + cp;
            vA = (c0 > cm) && (c0 > cp) && (p3A > g_athpow[f]);
        }
        f = lt + 128;
        if (f <= 255) {
            float dm = pw[team][f - 1], d0 = pw[team][f], dp = pw[team][f + 1];
            p3B = dm + d0 + dp;
            vB = (d0 > dm) && (d0 > dp) && (p3B > g_athpow[f]);
        }
    }
    unsigned mA = __ballot_sync(0xFFFFFFFFu, vA);
    unsigned mB = __ballot_sync(0xFFFFFFFFu, vB);
    if (l == 0) { cnt[team][w] = __popc(mA); cnt[team][4 + w] = __popc(mB); }
    BART();
    if (lt == 0) {
        int s = 0;
        for (int c = 0; c < 8; c++) { cbase[team][c] = s; s += cnt[team][c]; }
        nsh[team] = s;
    }
    BART();
    unsigned below = (1u << l) - 1u;
    if (vA) {
        int pos = cbase[team][w] + __popc(mA & below);
        order[team][pos] = (short)lt;
        mcv[team][pos]   = 10.f * log10f(p3A);
    }
    if (vB) {
        int pos = cbase[team][4 + w] + __popc(mB & below);
        order[team][pos] = (short)(lt + 128);
        mcv[team][pos]   = 10.f * log10f(p3B);
    }
    BART();

    // faithful sequential dedup (bark indexed by LIST POSITION, as in ref)
    if (lt == 0) {
        int n = nsh[team], ip = 0;
        for (int i = 1; i < n; i++) {
            if (sb[i] - sb[ip] < 0.5f) {
                if (mcv[team][ip] < mcv[team][i]) { keepf[team][ip] = 0; ip++; }
                else                               keepf[team][i]  = 0;
            } else ip = i;
        }
    }
    BART();

    // compact kept maskers (warp 0 of team), precompute exp2-folded constants
    if (lt < 32) {
        int n = nsh[team], basep = 0;
        for (int c0 = 0; c0 < n; c0 += 32) {
            int i = c0 + lt;
            bool ok = (i < n) && keepf[team][i];
            unsigned m = __ballot_sync(0xFFFFFFFFu, ok);
            if (ok) {
                int pos = basep + __popc(m & ((1u << lt) - 1u));
                int o = order[team][i];
                float mv = mcv[team][i];
                mz[team][pos]  = sb[o];
                mb2[team][pos] = (mv + g_dshift[o]) * LG;
                ms2[team][pos] = fmaf(0.37f, fmaxf(mv - 40.f, 0.f), -27.f) * LG;
            }
            basep += __popc(m);
        }
        if (lt == 0) Ksh[team] = basep;
    }
    BART();

    int K = Ksh[team];
    float sc = exp10f(fmaf(-0.1f, pm, 9.6f));
    const float SLP = 27.f * LG;
    const float* pdp = g_pdel + t * F;
    float lsum = 0.f;
    for (int f = lt; f < F; f += 128) {
        float bf  = sb[f];
        float sum = g_athpow[f];
        for (int k = 0; k < K; k++) {
            float dz = bf - mz[team][k];
            float sl = (dz > 0.f) ? ms2[team][k] : SLP;
            sum += exp2f(fmaf(sl, dz, mb2[team][k]));
        }
        float v = fmaf(sc, pdp[f], -sum);
        if (v > 0.f) lsum += v;
    }
#pragma unroll
    for (int o = 16; o > 0; o >>= 1)
        lsum += __shfl_xor_sync(0xFFFFFFFFu, lsum, o);
    if (l == 0) red[team][w] = lsum;
    BART();
    if (lt == 0)
        atomicAdd(&g_acc, (double)(red[team][0] + red[team][1]
                                 + red[team][2] + red[team][3]));
}

__global__ void finalize_kernel(float* out, int N) {
    out[0] = (float)(1e-6 * g_acc / (double)N);
}

// ---------------------------------------------------------------------------
extern "C" void kernel_launch(void* const* d_in, const int* in_sizes, int n_in,
                              void* d_out, int out_size)
{
    const float* xadv = (const float*)d_in[0];
    const float* xref = (const float*)d_in[1];
    float* out = (float*)d_out;

    int L = in_sizes[0];
    int T = (L - W) / HOP + 1;          // 1247 for L=160000
    if (T > MAXT) T = MAXT;
    int N  = T * F;
    int Lv = (T - 1) * HOP + W;
    int ng = (T + FT - 1) / FT;

    init_tables<<<1, 512>>>();
    stft_kernel<<<dim3(ng, 2), STHREADS>>>(xadv, xref, T, Lv);
    reduce_finish<<<1, 512>>>(ng * 2);
    thresh_kernel<<<(T + 1) / 2, 256>>>(T);
    finalize_kernel<<<1, 1>>>(out, N);
}

// round 6
// speedup vs baseline: 2.1649x; 1.0899x over previous
#include <cuda_runtime.h>
#include <math.h>

#define W 512
#define F 257
#define HOP 128
#define FT 4
#define MAXT 1300
#define SPAN (W + (FT - 1) * HOP)   // 896

__device__ __forceinline__ float ex2(float x) {
    float r; asm("ex2.approx.ftz.f32 %0, %1;" : "=f"(r) : "f"(x)); return r;
}
__device__ __forceinline__ float lg2(float x) {
    float r; asm("lg2.approx.ftz.f32 %0, %1;" : "=f"(r) : "f"(x)); return r;
}

// ---- static device scratch ----
__device__ float2 g_tw[544];           // padded: idx = k + (k>>4)
__device__ float  g_hann[512];
__device__ float  g_bark[F], g_dshift[F], g_athpow[F];
__device__ float  g_pr  [MAXT * F];
__device__ float  g_pdel[MAXT * F];
__device__ float  g_pmax_part[1024];
__device__ float  g_psd_max;
__device__ double g_acc;

// ---------------------------------------------------------------------------
__global__ void init_tables() {
    int i = threadIdx.x;
    if (i < 512) {
        double s, c;
        sincospi(2.0 * (double)i / 512.0, &s, &c);
        g_tw[i + (i >> 4)] = make_float2((float)c, (float)s);
        g_hann[i] = (float)(0.5 * (1.0 - cospi(2.0 * (double)i / 512.0)));
    }
    if (i < F) {
        double freq = (double)i * (8000.0 / 256.0);
        double bark = 13.0 * atan(0.00076 * freq)
                    + 3.5  * atan((freq / 7500.0) * (freq / 7500.0));
        float bf = (float)bark;
        g_bark[i]   = bf;
        g_dshift[i] = -6.025f - 0.275f * bf;
        if (freq >= 20.0 && freq <= 20000.0) {
            double fk = freq * 0.001;
            double ath = 3.64 * pow(fk, -0.8)
                       - 6.5  * exp(-0.6 * (fk - 3.3) * (fk - 3.3))
                       + 0.001 * fk * fk * fk * fk
                       - 12.0;
            g_athpow[i] = exp10f((float)ath * 0.1f);
        } else {
            g_athpow[i] = 0.0f;
        }
    }
}

// ---------------------------------------------------------------------------
// STFT: doubly-folded real DFT, 128 threads, one parity per CTA, FT frames.
// bins f = 2*tid + par; f=256 handled by bin256_kernel.
// ---------------------------------------------------------------------------
__global__ void __launch_bounds__(128) stft_kernel(
    const float* __restrict__ xadv, const float* __restrict__ xref,
    int T, int Lv)
{
    __shared__ float  xr[SPAN], xd[SPAN];
    __shared__ float4 eo[FT][128];
    __shared__ float  edge[FT][6];
    __shared__ float2 tw[544];
    __shared__ float  wmax[4];

    int tid = threadIdx.x;
    int par = blockIdx.y;
    int t0  = blockIdx.x * FT;
    int base = t0 * HOP;

    for (int k = tid; k < 512; k += 128) {
        int pk = k + (k >> 4);
        tw[pk] = g_tw[pk];
    }
    for (int i = tid; i < SPAN; i += 128) {
        int g = base + i;
        float r = 0.f, d = 0.f;
        if (g < Lv) { r = xref[g]; d = xadv[g] - r; }
        xr[i] = r; xd[i] = d;
    }
    __syncthreads();

    float s = par ? -1.f : 1.f;
    for (int idx = tid; idx < FT * 128; idx += 128) {
        int j = idx >> 7, n = idx & 127;
        const float* fr = xr + j * HOP;
        const float* fd = xd + j * HOP;
        if (n == 0) {
            edge[j][0] = fr[256];
            edge[j][1] = (fr[128] + fr[384]) * 0.5f;
            edge[j][2] = (fr[128] - fr[384]) * 0.5f;
            edge[j][3] = fd[256];
            edge[j][4] = (fd[128] + fd[384]) * 0.5f;
            edge[j][5] = (fd[128] - fd[384]) * 0.5f;
        } else {
            float h1 = g_hann[n], h2 = g_hann[256 - n];
            float a1 = fr[n], a2 = fr[512 - n], a3 = fr[256 - n], a4 = fr[256 + n];
            float b1 = fd[n], b2 = fd[512 - n], b3 = fd[256 - n], b4 = fd[256 + n];
            eo[j][n] = make_float4(
                (a1 + a2) * h1 + s * ((a3 + a4) * h2),
                (a1 - a2) * h1 - s * ((a3 - a4) * h2),
                (b1 + b2) * h1 + s * ((b3 + b4) * h2),
                (b1 - b2) * h1 - s * ((b3 - b4) * h2));
        }
    }
    __syncthreads();

    int i = tid, f = 2 * i + par;
    float sgn = (i & 1) ? -1.f : 1.f;
    float rr[FT], ii[FT], rd[FT], id_[FT];
#pragma unroll
    for (int j = 0; j < FT; j++) {
        if (par == 0) {
            rr[j]  = fmaf(sgn, edge[j][1], edge[j][0]);
            ii[j]  = 0.f;
            rd[j]  = fmaf(sgn, edge[j][4], edge[j][3]);
            id_[j] = 0.f;
        } else {
            rr[j]  = -edge[j][0];
            ii[j]  = sgn * edge[j][2];
            rd[j]  = -edge[j][3];
            id_[j] = sgn * edge[j][5];
        }
    }
    int k = f;
#pragma unroll 4
    for (int n = 1; n < 128; n++) {
        float2 cs = tw[k + (k >> 4)];
#pragma unroll
        for (int j = 0; j < FT; j++) {
            float4 v = eo[j][n];
            rr[j]  = fmaf(v.x, cs.x, rr[j]);
            ii[j]  = fmaf(v.y, cs.y, ii[j]);
            rd[j]  = fmaf(v.z, cs.x, rd[j]);
            id_[j] = fmaf(v.w, cs.y, id_[j]);
        }
        k = (k + f) & 511;
    }
    const float gw2 = 1.0172526041666667e-5f;   // (8/3)/512^2
    float lmax = 0.f;
#pragma unroll
    for (int j = 0; j < FT; j++) {
        int t = t0 + j;
        if (t < T) {
            float Pr = gw2 * (rr[j] * rr[j] + ii[j] * ii[j]);
            g_pr[t * F + f]   = Pr;
            lmax = fmaxf(lmax, Pr);
            g_pdel[t * F + f] = gw2 * (rd[j] * rd[j] + id_[j] * id_[j]);
        }
    }
#pragma unroll
    for (int o = 16; o > 0; o >>= 1)
        lmax = fmaxf(lmax, __shfl_xor_sync(0xFFFFFFFFu, lmax, o));
    if ((tid & 31) == 0) wmax[tid >> 5] = lmax;
    __syncthreads();
    if (tid == 0) {
        float m = fmaxf(fmaxf(wmax[0], wmax[1]), fmaxf(wmax[2], wmax[3]));
        g_pmax_part[blockIdx.y * gridDim.x + blockIdx.x] = m;
    }
}

// ---------------------------------------------------------------------------
// Bin 256: X[256] = sum (-1)^n h[n] x[n]. One warp per frame, 8 frames/CTA.
// ---------------------------------------------------------------------------
__global__ void __launch_bounds__(256) bin256_kernel(
    const float* __restrict__ xadv, const float* __restrict__ xref,
    int T, int off)
{
    __shared__ float sh[512];
    __shared__ float cmax[8];
    int tid = threadIdx.x, wid = tid >> 5, l = tid & 31;
    for (int n = tid; n < 512; n += 256)
        sh[n] = (n & 1) ? -g_hann[n] : g_hann[n];
    __syncthreads();

    int t = blockIdx.x * 8 + wid;
    float Pr = 0.f;
    if (t < T) {
        int base = t * HOP;
        float rr = 0.f, rd = 0.f;
        for (int n = l; n < 512; n += 32) {
            float w = sh[n];
            float r = xref[base + n], a = xadv[base + n];
            rr = fmaf(w, r, rr);
            rd = fmaf(w, a - r, rd);
        }
#pragma unroll
        for (int o = 16; o > 0; o >>= 1) {
            rr += __shfl_xor_sync(0xFFFFFFFFu, rr, o);
            rd += __shfl_xor_sync(0xFFFFFFFFu, rd, o);
        }
        const float gw2 = 1.0172526041666667e-5f;
        Pr = gw2 * rr * rr;
        if (l == 0) {
            g_pr[t * F + 256]   = Pr;
            g_pdel[t * F + 256] = gw2 * rd * rd;
        }
    }
    if (l == 0) cmax[wid] = Pr;
    __syncthreads();
    if (tid == 0) {
        float m = 0.f;
        for (int w = 0; w < 8; w++) m = fmaxf(m, cmax[w]);
        g_pmax_part[off + blockIdx.x] = m;
    }
}

// ---------------------------------------------------------------------------
__global__ void reduce_finish(int nb) {
    __shared__ float sm[512];
    int tid = threadIdx.x;
    float v = 0.f;
    for (int i = tid; i < nb; i += 512) v = fmaxf(v, g_pmax_part[i]);
    sm[tid] = v;
    __syncthreads();
    for (int s = 256; s > 0; s >>= 1) {
        if (tid < s) sm[tid] = fmaxf(sm[tid], sm[tid + s]);
        __syncthreads();
    }
    if (tid == 0) {
        g_psd_max = 10.f * log10f(fmaxf(sm[0], 1e-20f));
        g_acc = 0.0;
    }
}

// ---------------------------------------------------------------------------
// Threshold + fused loss. 128 threads, one frame per CTA.
// Upslope handled by extended-precision suffix sums (one exp2 per bin).
// ---------------------------------------------------------------------------
__global__ void __launch_bounds__(128) thresh_kernel(int T) {
    __shared__ float sb[F], pw[F];
    __shared__ float mcv[128];
    __shared__ short order[128], obk[128];
    __shared__ unsigned char keepf[128];
    __shared__ float mz[128], mb2[128], ms2[128];
    __shared__ float Um[129], Ue[129];
    __shared__ int   cnt[8], cbase[8];
    __shared__ int   nsh, Ksh;
    __shared__ float red[4];

    const float LG  = 0.33219280948873623f;   // 0.1*log2(10)
    const float SLP = 27.f * LG;
    const float DB2 = 3.0102999566398120f;    // 10/log2(10)

    int tid = threadIdx.x;
    int w = tid >> 5, l = tid & 31;
    int t = blockIdx.x;
    float pm = g_psd_max;
    float C = ex2(LG * (96.f - pm));

    const float* prp = g_pr + t * F;
    for (int f = tid; f < F; f += 128) {
        sb[f] = g_bark[f];
        pw[f] = C * fmaxf(prp[f], 1e-20f);
    }
    keepf[tid] = 1;
    __syncthreads();

    // local-max + ATH candidates: f=tid (chunk w), f=tid+128 (chunk 4+w)
    float p3A = 0.f, p3B = 0.f;
    bool  vA = false, vB = false;
    if (tid >= 1) {
        float a = pw[tid - 1], b = pw[tid], c = pw[tid + 1];
        p3A = a + b + c;
        vA = (b > a) && (b > c) && (p3A > g_athpow[tid]);
    }
    {
        int f = tid + 128;   // 128..255
        float a = pw[f - 1], b = pw[f], c = pw[f + 1];
        p3B = a + b + c;
        vB = (b > a) && (b > c) && (p3B > g_athpow[f]);
    }
    unsigned mA = __ballot_sync(0xFFFFFFFFu, vA);
    unsigned mB = __ballot_sync(0xFFFFFFFFu, vB);
    if (l == 0) { cnt[w] = __popc(mA); cnt[4 + w] = __popc(mB); }
    __syncthreads();
    if (tid == 0) {
        int s = 0;
        for (int c = 0; c < 8; c++) { cbase[c] = s; s += cnt[c]; }
        nsh = s;
    }
    __syncthreads();
    unsigned below = (1u << l) - 1u;
    if (vA) {
        int pos = cbase[w] + __popc(mA & below);
        order[pos] = (short)tid;
        mcv[pos]   = DB2 * lg2(p3A);
    }
    if (vB) {
        int pos = cbase[4 + w] + __popc(mB & below);
        order[pos] = (short)(tid + 128);
        mcv[pos]   = DB2 * lg2(p3B);
    }
    __syncthreads();

    // faithful sequential dedup (bark indexed by LIST POSITION, as in ref)
    if (tid == 0) {
        int n = nsh, ip = 0;
        for (int i = 1; i < n; i++) {
            if (sb[i] - sb[ip] < 0.5f) {
                if (mcv[ip] < mcv[i]) { keepf[ip] = 0; ip++; }
                else                    keepf[i]  = 0;
            } else ip = i;
        }
    }
    __syncthreads();

    // compact kept maskers (warp 0), then suffix sums (thread 0)
    if (tid < 32) {
        int n = nsh, basep = 0;
        for (int c0 = 0; c0 < n; c0 += 32) {
            int i = c0 + tid;
            bool ok = (i < n) && keepf[i];
            unsigned m = __ballot_sync(0xFFFFFFFFu, ok);
            if (ok) {
                int pos = basep + __popc(m & ((1u << tid) - 1u));
                int o = order[i];
                float mv = mcv[i];
                obk[pos] = (short)o;
                mz[pos]  = sb[o];
                mb2[pos] = (mv + g_dshift[o]) * LG;
                ms2[pos] = fmaf(0.37f, fmaxf(mv - 40.f, 0.f), -27.f) * LG;
            }
            basep += __popc(m);
        }
        __syncwarp();
        if (tid == 0) {
            int K = basep;
            Ksh = K;
            float S = 0.f, E = -1e30f;
            Um[K] = 0.f; Ue[K] = E;
            for (int kk = K - 1; kk >= 0; kk--) {
                float e = fmaf(-SLP, mz[kk], mb2[kk]);
                float En = fmaxf(E, e);
                S = S * ex2(E - En) + ex2(e - En);
                E = En;
                Um[kk] = S; Ue[kk] = E;
            }
        }
    }
    __syncthreads();

    int K = Ksh;
    // sc = 10^(9.6 - pm/10) = 2^(9.6*log2(10) - LG*pm); 9.6*log2(10) = 31.890509711463527
    float sc = ex2(fmaf(-LG, pm, 31.890509711463527f));
    const float* pdp = g_pdel + t * F;
    float lsum = 0.f;
    for (int f = tid; f < F; f += 128) {
        float bf = sb[f];
        // j0 = #maskers with bin < f (binary search)
        int lo = 0, hi = K;
        while (lo < hi) {
            int mid = (lo + hi) >> 1;
            if (obk[mid] < f) lo = mid + 1; else hi = mid;
        }
        int j0 = lo;
        float sum = g_athpow[f];
        for (int kk = 0; kk < j0; kk++) {
            float dz = bf - mz[kk];
            sum += ex2(fmaf(ms2[kk], dz, mb2[kk]));
        }
        sum += Um[j0] * ex2(fmaf(SLP, bf, Ue[j0]));
        float v = fmaf(sc, pdp[f], -sum);
        if (v > 0.f) lsum += v;
    }
#pragma unroll
    for (int o = 16; o > 0; o >>= 1)
        lsum += __shfl_xor_sync(0xFFFFFFFFu, lsum, o);
    if (l == 0) red[w] = lsum;
    __syncthreads();
    if (tid == 0)
        atomicAdd(&g_acc, (double)(red[0] + red[1] + red[2] + red[3]));
}

__global__ void finalize_kernel(float* out, int N) {
    out[0] = (float)(1e-6 * g_acc / (double)N);
}

// ---------------------------------------------------------------------------
extern "C" void kernel_launch(void* const* d_in, const int* in_sizes, int n_in,
                              void* d_out, int out_size)
{
    const float* xadv = (const float*)d_in[0];
    const float* xref = (const float*)d_in[1];
    float* out = (float*)d_out;

    int L = in_sizes[0];
    int T = (L - W) / HOP + 1;
    if (T > MAXT) T = MAXT;
    int N  = T * F;
    int Lv = (T - 1) * HOP + W;
    int ng = (T + FT - 1) / FT;
    int nb256 = (T + 7) / 8;

    init_tables<<<1, 512>>>();
    stft_kernel<<<dim3(ng, 2), 128>>>(xadv, xref, T, Lv);
    bin256_kernel<<<nb256, 256>>>(xadv, xref, T, ng * 2);
    reduce_finish<<<1, 512>>>(ng * 2 + nb256);
    thresh_kernel<<<T, 128>>>(T);
    finalize_kernel<<<1, 1>>>(out, N);
}

// round 7
// speedup vs baseline: 3.1636x; 1.4613x over previous
#include <cuda_runtime.h>
#include <math.h>

#define W 512
#define F 257
#define HOP 128
#define FT 4
#define MAXT 1300
#define SPAN (W + (FT - 1) * HOP)   // 896

typedef unsigned long long ull;

__device__ __forceinline__ float ex2(float x) {
    float r; asm("ex2.approx.ftz.f32 %0, %1;" : "=f"(r) : "f"(x)); return r;
}
__device__ __forceinline__ float lg2(float x) {
    float r; asm("lg2.approx.ftz.f32 %0, %1;" : "=f"(r) : "f"(x)); return r;
}
__device__ __forceinline__ ull pack2(float lo, float hi) {
    ull r; asm("mov.b64 %0, {%1, %2};" : "=l"(r) : "f"(lo), "f"(hi)); return r;
}
__device__ __forceinline__ void unpack2(ull v, float &lo, float &hi) {
    asm("mov.b64 {%0, %1}, %2;" : "=f"(lo), "=f"(hi) : "l"(v));
}
__device__ __forceinline__ void ffma2(ull &acc, ull a, ull b) {
    asm("fma.rn.f32x2 %0, %1, %2, %0;" : "+l"(acc) : "l"(a), "l"(b));
}

// ---- static device scratch ----
struct Ctl { double acc; unsigned int pmaxi; unsigned int done; };
__device__ Ctl   g_ctl;
__device__ float g_bark[F], g_dshift[F], g_athpow[F];
__device__ float g_pr  [MAXT * F];
__device__ float g_pdel[MAXT * F];

// ---------------------------------------------------------------------------
// Mega STFT kernel. blockIdx.y: 0/1 = DFT parity CTAs, 2 = bin256 + tables.
// ---------------------------------------------------------------------------
__global__ void __launch_bounds__(128) stft_kernel(
    const float* __restrict__ xadv, const float* __restrict__ xref,
    int T, int Lv)
{
    int tid = threadIdx.x;
    int par = blockIdx.y;
    int t0  = blockIdx.x * FT;

    if (par == 2) {
        // ---- bin 256 (one warp per frame) + constant tables (CTA x==0) ----
        int wid = tid >> 5, l = tid & 31;
        int t = t0 + wid;
        float Pr = 0.f;
        if (t < T) {
            int base = t * HOP;
            float rr = 0.f, rd = 0.f;
            for (int n = l; n < 512; n += 32) {
                float hw = 0.5f - 0.5f * cospif((float)n * (1.f / 256.f));
                if (n & 1) hw = -hw;
                float r = xref[base + n], a = xadv[base + n];
                rr = fmaf(hw, r, rr);
                rd = fmaf(hw, a - r, rd);
            }
#pragma unroll
            for (int o = 16; o > 0; o >>= 1) {
                rr += __shfl_xor_sync(0xFFFFFFFFu, rr, o);
                rd += __shfl_xor_sync(0xFFFFFFFFu, rd, o);
            }
            const float gw2 = 1.0172526041666667e-5f;
            Pr = gw2 * rr * rr;
            if (l == 0) {
                g_pr[t * F + 256]   = Pr;
                g_pdel[t * F + 256] = gw2 * rd * rd;
                atomicMax(&g_ctl.pmaxi, __float_as_uint(Pr));
            }
        }
        if (blockIdx.x == 0) {
            for (int i = tid; i < F; i += 128) {
                double freq = (double)i * (8000.0 / 256.0);
                double bark = 13.0 * atan(0.00076 * freq)
                            + 3.5  * atan((freq / 7500.0) * (freq / 7500.0));
                float bf = (float)bark;
                g_bark[i]   = bf;
                g_dshift[i] = -6.025f - 0.275f * bf;
                if (freq >= 20.0 && freq <= 20000.0) {
                    double fk = freq * 0.001;
                    double ath = 3.64 * pow(fk, -0.8)
                               - 6.5  * exp(-0.6 * (fk - 3.3) * (fk - 3.3))
                               + 0.001 * fk * fk * fk * fk
                               - 12.0;
                    g_athpow[i] = exp10f((float)ath * 0.1f);
                } else {
                    g_athpow[i] = 0.0f;
                }
            }
        }
        return;
    }

    // ---- folded real DFT ----
    __shared__ float      xr[SPAN], xd[SPAN];
    __shared__ ulonglong2 eo[FT][128];      // (e_ref,e_del) , (o_ref,o_del)
    __shared__ float      edge[FT][6];
    __shared__ ull        twc[544], tws[544];  // packed (c,c),(s,s); idx k+(k>>4)
    __shared__ float      wmax[4];

    int base = t0 * HOP;

    for (int k = tid; k < 512; k += 128) {
        float s, c;
        sincospif((float)k * (1.f / 256.f), &s, &c);
        int pk = k + (k >> 4);
        twc[pk] = pack2(c, c);
        tws[pk] = pack2(s, s);
    }
    for (int i = tid; i < SPAN; i += 128) {
        int g = base + i;
        float r = 0.f, d = 0.f;
        if (g < Lv) { r = xref[g]; d = xadv[g] - r; }
        xr[i] = r; xd[i] = d;
    }
    __syncthreads();

    float s = par ? -1.f : 1.f;
    for (int idx = tid; idx < FT * 128; idx += 128) {
        int j = idx >> 7, n = idx & 127;
        const float* fr = xr + j * HOP;
        const float* fd = xd + j * HOP;
        if (n == 0) {
            edge[j][0] = fr[256];
            edge[j][1] = (fr[128] + fr[384]) * 0.5f;
            edge[j][2] = (fr[128] - fr[384]) * 0.5f;
            edge[j][3] = fd[256];
            edge[j][4] = (fd[128] + fd[384]) * 0.5f;
            edge[j][5] = (fd[128] - fd[384]) * 0.5f;
        } else {
            float h1 = 0.5f - 0.5f * cospif((float)n * (1.f / 256.f));
            float h2 = 0.5f - 0.5f * cospif((float)(256 - n) * (1.f / 256.f));
            float a1 = fr[n], a2 = fr[512 - n], a3 = fr[256 - n], a4 = fr[256 + n];
            float b1 = fd[n], b2 = fd[512 - n], b3 = fd[256 - n], b4 = fd[256 + n];
            float er = (a1 + a2) * h1 + s * ((a3 + a4) * h2);
            float orf = (a1 - a2) * h1 - s * ((a3 - a4) * h2);
            float ed = (b1 + b2) * h1 + s * ((b3 + b4) * h2);
            float od = (b1 - b2) * h1 - s * ((b3 - b4) * h2);
            ulonglong2 u;
            u.x = pack2(er, ed);
            u.y = pack2(orf, od);
            eo[j][n] = u;
        }
    }
    __syncthreads();

    int f = 2 * tid + par;
    float sgn = (tid & 1) ? -1.f : 1.f;
    ull accR[FT], accI[FT];
#pragma unroll
    for (int j = 0; j < FT; j++) {
        if (par == 0) {
            accR[j] = pack2(fmaf(sgn, edge[j][1], edge[j][0]),
                            fmaf(sgn, edge[j][4], edge[j][3]));
            accI[j] = pack2(0.f, 0.f);
        } else {
            accR[j] = pack2(-edge[j][0], -edge[j][3]);
            accI[j] = pack2(sgn * edge[j][2], sgn * edge[j][5]);
        }
    }
    int k = f;
#pragma unroll 4
    for (int n = 1; n < 128; n++) {
        int pk = k + (k >> 4);
        ull cc = twc[pk], ss = tws[pk];
#pragma unroll
        for (int j = 0; j < FT; j++) {
            ulonglong2 v = eo[j][n];
            ffma2(accR[j], v.x, cc);
            ffma2(accI[j], v.y, ss);
        }
        k = (k + f) & 511;
    }
    const float gw2 = 1.0172526041666667e-5f;   // (8/3)/512^2
    float lmax = 0.f;
#pragma unroll
    for (int j = 0; j < FT; j++) {
        int t = t0 + j;
        if (t < T) {
            float rr, rd, ii, id_;
            unpack2(accR[j], rr, rd);
            unpack2(accI[j], ii, id_);
            float Pr = gw2 * (rr * rr + ii * ii);
            g_pr[t * F + f]   = Pr;
            lmax = fmaxf(lmax, Pr);
            g_pdel[t * F + f] = gw2 * (rd * rd + id_ * id_);
        }
    }
#pragma unroll
    for (int o = 16; o > 0; o >>= 1)
        lmax = fmaxf(lmax, __shfl_xor_sync(0xFFFFFFFFu, lmax, o));
    if ((tid & 31) == 0) wmax[tid >> 5] = lmax;
    __syncthreads();
    if (tid == 0) {
        float m = fmaxf(fmaxf(wmax[0], wmax[1]), fmaxf(wmax[2], wmax[3]));
        atomicMax(&g_ctl.pmaxi, __float_as_uint(m));
    }
}

// ---------------------------------------------------------------------------
// Threshold + fused loss + last-block finalize. One frame per CTA.
// ---------------------------------------------------------------------------
__global__ void __launch_bounds__(128) thresh_kernel(float* out, int T, int N) {
    __shared__ float sb[F], pw[F];
    __shared__ float mcv[128];
    __shared__ short order[128], obk[128];
    __shared__ unsigned char keepf[128];
    __shared__ float mz[128], mb2[128], ms2[128];
    __shared__ float Um[129], Ue[129];
    __shared__ int   cnt[8], cbase[8];
    __shared__ int   nsh, Ksh;
    __shared__ float red[4];

    const float LG  = 0.33219280948873623f;   // 0.1*log2(10)
    const float SLP = 27.f * LG;
    const float DB2 = 3.0102999566398120f;    // 10/log2(10)

    int tid = threadIdx.x;
    int w = tid >> 5, l = tid & 31;
    int t = blockIdx.x;

    // SC = 10^9.6 / Pmax  (== 10^((96-pm)/10) == 10^(9.6-pm/10))
    float Pmax = fmaxf(__uint_as_float(g_ctl.pmaxi), 1e-20f);
    float SC = ex2(31.890509711463527f - lg2(Pmax));

    const float* prp = g_pr + t * F;
    for (int f = tid; f < F; f += 128) {
        sb[f] = g_bark[f];
        pw[f] = SC * fmaxf(prp[f], 1e-20f);
    }
    keepf[tid] = 1;
    __syncthreads();

    // local-max + ATH candidates: f=tid (chunk w), f=tid+128 (chunk 4+w)
    float p3A = 0.f, p3B = 0.f;
    bool  vA = false, vB = false;
    if (tid >= 1) {
        float a = pw[tid - 1], b = pw[tid], c = pw[tid + 1];
        p3A = a + b + c;
        vA = (b > a) && (b > c) && (p3A > g_athpow[tid]);
    }
    {
        int f = tid + 128;   // 128..255
        float a = pw[f - 1], b = pw[f], c = pw[f + 1];
        p3B = a + b + c;
        vB = (b > a) && (b > c) && (p3B > g_athpow[f]);
    }
    unsigned mA = __ballot_sync(0xFFFFFFFFu, vA);
    unsigned mB = __ballot_sync(0xFFFFFFFFu, vB);
    if (l == 0) { cnt[w] = __popc(mA); cnt[4 + w] = __popc(mB); }
    __syncthreads();
    if (tid == 0) {
        int s = 0;
        for (int c = 0; c < 8; c++) { cbase[c] = s; s += cnt[c]; }
        nsh = s;
    }
    __syncthreads();
    unsigned below = (1u << l) - 1u;
    if (vA) {
        int pos = cbase[w] + __popc(mA & below);
        order[pos] = (short)tid;
        mcv[pos]   = DB2 * lg2(p3A);
    }
    if (vB) {
        int pos = cbase[4 + w] + __popc(mB & below);
        order[pos] = (short)(tid + 128);
        mcv[pos]   = DB2 * lg2(p3B);
    }
    __syncthreads();

    // faithful sequential dedup (bark indexed by LIST POSITION, as in ref)
    if (tid == 0) {
        int n = nsh, ip = 0;
        for (int i = 1; i < n; i++) {
            if (sb[i] - sb[ip] < 0.5f) {
                if (mcv[ip] < mcv[i]) { keepf[ip] = 0; ip++; }
                else                    keepf[i]  = 0;
            } else ip = i;
        }
    }
    __syncthreads();

    // compact kept maskers (warp 0), then suffix sums (thread 0)
    if (tid < 32) {
        int n = nsh, basep = 0;
        for (int c0 = 0; c0 < n; c0 += 32) {
            int i = c0 + tid;
            bool ok = (i < n) && keepf[i];
            unsigned m = __ballot_sync(0xFFFFFFFFu, ok);
            if (ok) {
                int pos = basep + __popc(m & ((1u << tid) - 1u));
                int o = order[i];
                float mv = mcv[i];
                obk[pos] = (short)o;
                mz[pos]  = sb[o];
                mb2[pos] = (mv + g_dshift[o]) * LG;
                ms2[pos] = fmaf(0.37f, fmaxf(mv - 40.f, 0.f), -27.f) * LG;
            }
            basep += __popc(m);
        }
        __syncwarp();
        if (tid == 0) {
            int K = basep;
            Ksh = K;
            float S = 0.f, E = -1e30f;
            Um[K] = 0.f; Ue[K] = E;
            for (int kk = K - 1; kk >= 0; kk--) {
                float e = fmaf(-SLP, mz[kk], mb2[kk]);
                float En = fmaxf(E, e);
                S = S * ex2(E - En) + ex2(e - En);
                E = En;
                Um[kk] = S; Ue[kk] = E;
            }
        }
    }
    __syncthreads();

    int K = Ksh;
    const float* pdp = g_pdel + t * F;
    float lsum = 0.f;
    for (int f = tid; f < F; f += 128) {
        float bf = sb[f];
        int lo = 0, hi = K;
        while (lo < hi) {
            int mid = (lo + hi) >> 1;
            if (obk[mid] < f) lo = mid + 1; else hi = mid;
        }
        int j0 = lo;
        float sum = g_athpow[f];
        for (int kk = 0; kk < j0; kk++) {
            float dz = bf - mz[kk];
            sum += ex2(fmaf(ms2[kk], dz, mb2[kk]));
        }
        sum += Um[j0] * ex2(fmaf(SLP, bf, Ue[j0]));
        float v = fmaf(SC, pdp[f], -sum);
        if (v > 0.f) lsum += v;
    }
#pragma unroll
    for (int o = 16; o > 0; o >>= 1)
        lsum += __shfl_xor_sync(0xFFFFFFFFu, lsum, o);
    if (l == 0) red[w] = lsum;
    __syncthreads();
    if (tid == 0) {
        atomicAdd(&g_ctl.acc, (double)(red[0] + red[1] + red[2] + red[3]));
        __threadfence();
        unsigned d = atomicAdd(&g_ctl.done, 1u);
        if (d == (unsigned)(gridDim.x - 1)) {
            double acc = g_ctl.acc;
            out[0] = (float)(1e-6 * acc / (double)N);
        }
    }
}

// ---------------------------------------------------------------------------
extern "C" void kernel_launch(void* const* d_in, const int* in_sizes, int n_in,
                              void* d_out, int out_size)
{
    const float* xadv = (const float*)d_in[0];
    const float* xref = (const float*)d_in[1];
    float* out = (float*)d_out;

    int L = in_sizes[0];
    int T = (L - W) / HOP + 1;
    if (T > MAXT) T = MAXT;
    int N  = T * F;
    int Lv = (T - 1) * HOP + W;
    int ng = (T + FT - 1) / FT;

    void* ctl_addr = nullptr;
    cudaGetSymbolAddress(&ctl_addr, g_ctl);
    cudaMemsetAsync(ctl_addr, 0, sizeof(Ctl));

    stft_kernel<<<dim3(ng, 3), 128>>>(xadv, xref, T, Lv);
    thresh_kernel<<<T, 128>>>(out, T, N);
}